// round 14
// baseline (speedup 1.0000x reference)
#include <cuda_runtime.h>
#include <cuda_fp16.h>
#include <cstdint>

#define BB 64
#define LL 128
#define HH 1024
#define TT 256

#define NCTA 128
#define NTHR 256
#define UPB 8             // hidden units per CTA
#define MR 32             // gate rows per CTA (4 gates x 8 units)
#define KC 64             // K per chunk
#define NCH 16            // chunks per step

#define WT_B 4096         // W tile bytes: 32 rows x 128B (one chunk)
#define WSLICE_B 65536    // per-CTA W hi (or lo) slice: 16 chunks x 4KB
#define HT_B 8192         // h tile bytes: 64 rows x 128B

// smem byte offsets (k3)
#define SM_W    0                       // Whi[16 tiles] | Wlo[16 tiles] = 131072
#define SM_RING 131072                  // 4 x 8192 = 32768
#define SM_XG   163840                  // 32*66 floats = 8448
#define SM_RED  172288                  // 2*32*66 floats = 16896
#define SM_CST  189184                  // 8*64 floats = 2048
#define SM_WO   191232                  // 8 floats = 32
#define SM_PR   191296                  // 4*64 floats = 1024
#define SMEM_TOTAL 192320

#define RST 66

// ---------------- device scratch ----------------
__device__ __align__(16) __half g_Whi[NCTA*NCH*MR*KC];   // 8MB swizzled tiles
__device__ __align__(16) __half g_Wlo[NCTA*NCH*MR*KC];
__device__ __align__(16) __half g_hhi[2*NCH*KC*BB];      // ping-pong swizzled h [k][b]
__device__ float g_hiddenT[HH*BB];           // [k][b] transposed hidden
__device__ float g_xg[4*HH*BB];              // [gate_row][b]
__device__ float g_partial[NCTA*TT*BB];
__device__ unsigned g_cflag[NCH];            // per-chunk producer counters (monotonic)

// ---------------- helpers ----------------
__device__ __forceinline__ uint32_t smem_u32(const void* p) {
    uint32_t a;
    asm("{ .reg .u64 t; cvta.to.shared.u64 t, %1; cvt.u32.u64 %0, t; }" : "=r"(a) : "l"(p));
    return a;
}
__device__ __forceinline__ void cp16(void* dst, const void* src) {
    unsigned sa = (unsigned)__cvta_generic_to_shared(dst);
    asm volatile("cp.async.cg.shared.global [%0], [%1], 16;" :: "r"(sa), "l"(src));
}
__device__ __forceinline__ uint32_t sw128(uint32_t o) { return o ^ ((o >> 3) & 0x70); }

__device__ __forceinline__ void ldsm4(uint32_t* r, uint32_t a) {
    asm volatile("ldmatrix.sync.aligned.m8n8.x4.shared.b16 {%0,%1,%2,%3}, [%4];"
        : "=r"(r[0]), "=r"(r[1]), "=r"(r[2]), "=r"(r[3]) : "r"(a));
}
__device__ __forceinline__ void ldsm4t(uint32_t* r, uint32_t a) {
    asm volatile("ldmatrix.sync.aligned.m8n8.x4.trans.shared.b16 {%0,%1,%2,%3}, [%4];"
        : "=r"(r[0]), "=r"(r[1]), "=r"(r[2]), "=r"(r[3]) : "r"(a));
}
__device__ __forceinline__ void mma16816(float* d, const uint32_t* a, uint32_t b0, uint32_t b1) {
    asm volatile("mma.sync.aligned.m16n8k16.row.col.f32.f16.f16.f32 "
        "{%0,%1,%2,%3}, {%4,%5,%6,%7}, {%8,%9}, {%0,%1,%2,%3};"
        : "+f"(d[0]), "+f"(d[1]), "+f"(d[2]), "+f"(d[3])
        : "r"(a[0]), "r"(a[1]), "r"(a[2]), "r"(a[3]), "r"(b0), "r"(b1));
}
__device__ __forceinline__ float sigm(float x) { return 1.0f / (1.0f + __expf(-x)); }
__device__ __forceinline__ float ftanh(float x) { return 1.0f - 2.0f / (__expf(2.0f * x) + 1.0f); }

// ---------------- kW: split W_hh -> fp16 hi/lo swizzled tiles (8 k / thread) ----------------
__global__ void kW(const float* __restrict__ W_hh) {
    int idx = blockIdx.x * 256 + threadIdx.x;       // 524288 threads
    int R = idx >> 7;           // gate row 0..4095
    int k0 = (idx & 127) * 8;   // first of 8 consecutive k
    int gate = R >> 10;
    int u = R & 1023;
    int cta = u >> 3, j = u & 7;
    int m = gate * 8 + j;       // local row 0..31
    int ch = k0 >> 6, col = k0 & 63;
    uint32_t sw = sw128((uint32_t)(m * 128 + col * 2));   // 16B-aligned, chunk-contiguous
    const float4* src = (const float4*)(W_hh + (size_t)R * HH + k0);
    float4 a = src[0], b = src[1];
    float v[8] = {a.x, a.y, a.z, a.w, b.x, b.y, b.z, b.w};
    __half hi[8]; __half lo[8];
#pragma unroll
    for (int i = 0; i < 8; ++i) {
        hi[i] = __float2half_rn(v[i]);
        lo[i] = __float2half_rn(v[i] - __half2float(hi[i]));
    }
    size_t tb = (size_t)(cta * NCH + ch) * WT_B;
    *(uint4*)((char*)g_Whi + tb + sw) = *(const uint4*)hi;
    *(uint4*)((char*)g_Wlo + tb + sw) = *(const uint4*)lo;
}

// ---------------- k0: zero h buffers + chunk flags ----------------
__global__ void k0_init() {
    int g = blockIdx.x * blockDim.x + threadIdx.x;  // 131072
    if (g < 2 * NCH * KC * BB) g_hhi[g] = __float2half_rn(0.0f);
    if (g < NCH) g_cflag[g] = 0u;
}

// ---------------- k1: hidden (transposed [k][b] output) ----------------
__global__ void k1_hidden(const float* __restrict__ latent,
                          const float* __restrict__ W_lin,
                          const float* __restrict__ b_lin) {
    int g = blockIdx.x * blockDim.x + threadIdx.x;
    int k = g >> 6, b = g & 63;
    float acc = b_lin[k];
    const float* lr = latent + b * LL;
    const float* wr = W_lin + k * LL;
#pragma unroll 8
    for (int l = 0; l < LL; ++l) acc += lr[l] * wr[l];
    g_hiddenT[k * BB + b] = acc;
}

// ---------------- k2: x_gates, smem-staged hidden, 4 rows/thread ----------------
__global__ void k2_xgates(const float* __restrict__ W_ih,
                          const float* __restrict__ b_ih,
                          const float* __restrict__ b_hh) {
    __shared__ float sh[KC * BB];    // 16KB
    const int tid = threadIdx.x;
    const int rr = tid >> 6, b = tid & 63;
    const int r0 = blockIdx.x * 16 + rr;      // grid 256; rows r0, r0+4, r0+8, r0+12
    float acc[4];
#pragma unroll
    for (int i = 0; i < 4; ++i) acc[i] = b_ih[r0 + 4 * i] + b_hh[r0 + 4 * i];
    const float4* w0 = (const float4*)(W_ih + (size_t)(r0)      * HH);
    const float4* w1 = (const float4*)(W_ih + (size_t)(r0 + 4)  * HH);
    const float4* w2 = (const float4*)(W_ih + (size_t)(r0 + 8)  * HH);
    const float4* w3 = (const float4*)(W_ih + (size_t)(r0 + 12) * HH);

    for (int ch = 0; ch < NCH; ++ch) {
        __syncthreads();
        const float4* src = (const float4*)(g_hiddenT + ch * KC * BB);
        float4* dst = (float4*)sh;
#pragma unroll
        for (int i = 0; i < 4; ++i) dst[tid + i * 256] = src[tid + i * 256];
        __syncthreads();
#pragma unroll
        for (int kq = 0; kq < 16; ++kq) {
            float4 wa = w0[ch * 16 + kq];
            float4 wb = w1[ch * 16 + kq];
            float4 wc = w2[ch * 16 + kq];
            float4 wd = w3[ch * 16 + kq];
            float h0 = sh[(kq * 4 + 0) * BB + b];
            float h1 = sh[(kq * 4 + 1) * BB + b];
            float h2 = sh[(kq * 4 + 2) * BB + b];
            float h3 = sh[(kq * 4 + 3) * BB + b];
            acc[0] += h0 * wa.x + h1 * wa.y + h2 * wa.z + h3 * wa.w;
            acc[1] += h0 * wb.x + h1 * wb.y + h2 * wb.z + h3 * wb.w;
            acc[2] += h0 * wc.x + h1 * wc.y + h2 * wc.z + h3 * wc.w;
            acc[3] += h0 * wd.x + h1 * wd.y + h2 * wd.z + h3 * wd.w;
        }
    }
#pragma unroll
    for (int i = 0; i < 4; ++i) g_xg[(size_t)(r0 + 4 * i) * BB + b] = acc[i];
}

// ---------------- chunk loader: poll producer flag, then 8KB cp.async ----------------
__device__ __forceinline__ void load_chunk(char* sm, int ping, int c, int tid, unsigned tgt) {
    if (tgt) {
        while (*(volatile unsigned*)&g_cflag[c] < tgt) { }
    }
    char* st = sm + SM_RING + (c & 3) * HT_B;
    const char* hh = (const char*)g_hhi + (size_t)(ping * NCH + c) * HT_B;
    int o = tid * 16;
    cp16(st + o, hh + o);
    cp16(st + 4096 + o, hh + 4096 + o);
    asm volatile("cp.async.commit_group;");
}

// ---------------- k3: persistent HMMA LSTM, W resident, dataflow sync ----------------
__global__ void __launch_bounds__(NTHR, 1)
k3_lstm(const float* __restrict__ W_out) {
    extern __shared__ char sm[];
    uint32_t smb = smem_u32(sm);
    float* wo  = (float*)(sm + SM_WO);
    float* cst = (float*)(sm + SM_CST);
    float* xgs = (float*)(sm + SM_XG);
    float* red0 = (float*)(sm + SM_RED);
    float* red1 = red0 + MR * RST;
    float* pr  = (float*)(sm + SM_PR);

    const int tid = threadIdx.x, blk = blockIdx.x;
    const int wid = tid >> 5, lane = tid & 31;
    const int ks = wid & 1;            // K-slice (k32)
    const int ng = (wid >> 1) & 1;     // N-half (n32)
    const int mh = wid >> 2;           // M-half (m16)
    const int u0 = blk * UPB;
    const int mychunk = blk >> 3;      // chunk this CTA's h units live in

    // per-lane swizzled ldmatrix offsets (within a 4KB W tile / 8KB h tile)
    uint32_t offA[2], offB[2][2];
#pragma unroll
    for (int kt = 0; kt < 2; ++kt) {
        uint32_t o = (uint32_t)((mh * 16 + (lane & 15)) * 128 + ks * 64 + kt * 32 + (lane >> 4) * 16);
        offA[kt] = sw128(o);
    }
#pragma unroll
    for (int kt = 0; kt < 2; ++kt)
#pragma unroll
        for (int np = 0; np < 2; ++np) {
            uint32_t o = (uint32_t)((ks * 32 + kt * 16 + (lane & 15)) * 128 + ng * 64 + np * 32 + (lane >> 4) * 16);
            offB[kt][np] = sw128(o);
        }

    // ---- prologue: W hi/lo slice -> smem (once), x_gates slice, c-state ----
    {
        const char* wh = (const char*)g_Whi + (size_t)blk * WSLICE_B;
        const char* wl = (const char*)g_Wlo + (size_t)blk * WSLICE_B;
#pragma unroll
        for (int i = 0; i < 16; ++i) {
            int o = (tid + i * NTHR) * 16;
            cp16(sm + SM_W + o, wh + o);
            cp16(sm + SM_W + WSLICE_B + o, wl + o);
        }
        asm volatile("cp.async.commit_group;");
    }
    for (int idx = tid; idx < MR * BB; idx += NTHR) {
        int m = idx >> 6, b = idx & 63;
        int gate = m >> 3, j = m & 7;
        xgs[m * RST + b] = g_xg[(size_t)(gate * HH + u0 + j) * BB + b];
    }
    if (tid < UPB) wo[tid] = W_out[u0 + tid];
    for (int i = tid; i < UPB * BB; i += NTHR) cst[i] = 0.0f;
    asm volatile("cp.async.wait_group 0;");
    __syncthreads();

    for (int t = 0; t < TT; ++t) {
        const int ping = t & 1;
        const unsigned tgt = 8u * (unsigned)t;

        load_chunk(sm, ping, 0, tid, tgt);
        load_chunk(sm, ping, 1, tid, tgt);
        load_chunk(sm, ping, 2, tid, tgt);

        // separate hi/lo accumulator banks (8 independent mma chains)
        float ah[4][4], al[4][4];
#pragma unroll
        for (int n = 0; n < 4; ++n)
#pragma unroll
            for (int q = 0; q < 4; ++q) { ah[n][q] = 0.0f; al[n][q] = 0.0f; }

        for (int c = 0; c < NCH; ++c) {
            if (c <= 13)      asm volatile("cp.async.wait_group 2;");
            else if (c == 14) asm volatile("cp.async.wait_group 1;");
            else              asm volatile("cp.async.wait_group 0;");
            __syncthreads();

            const uint32_t wbase = smb + SM_W + (uint32_t)(c * WT_B);
            const uint32_t hbase = smb + SM_RING + (uint32_t)((c & 3) * HT_B);
#pragma unroll
            for (int kt = 0; kt < 2; ++kt) {
                uint32_t Ahi[4], Alo[4], B0[4], B1[4];
                ldsm4(Ahi, wbase + offA[kt]);
                ldsm4(Alo, wbase + WSLICE_B + offA[kt]);
                ldsm4t(B0, hbase + offB[kt][0]);
                ldsm4t(B1, hbase + offB[kt][1]);
                mma16816(ah[0], Ahi, B0[0], B0[1]);
                mma16816(ah[1], Ahi, B0[2], B0[3]);
                mma16816(ah[2], Ahi, B1[0], B1[1]);
                mma16816(ah[3], Ahi, B1[2], B1[3]);
                mma16816(al[0], Alo, B0[0], B0[1]);
                mma16816(al[1], Alo, B0[2], B0[3]);
                mma16816(al[2], Alo, B1[0], B1[1]);
                mma16816(al[3], Alo, B1[2], B1[3]);
            }

            if (c + 3 < NCH) load_chunk(sm, ping, c + 3, tid, tgt);
        }

        // ---- store combined partials to red[ks] ----
        {
            float* rd = ks ? red1 : red0;
            const int r0 = lane >> 2, c0 = (lane & 3) * 2;
#pragma unroll
            for (int n = 0; n < 4; ++n) {
                int row = mh * 16 + r0;
                int col = ng * 32 + n * 8 + c0;
                rd[row * RST + col]           = ah[n][0] + al[n][0];
                rd[row * RST + col + 1]       = ah[n][1] + al[n][1];
                rd[(row + 8) * RST + col]     = ah[n][2] + al[n][2];
                rd[(row + 8) * RST + col + 1] = ah[n][3] + al[n][3];
            }
        }
        __syncthreads();

        // ---- gates + state update: 512 states, 2 per thread; no atomics ----
        {
            const int pingN = ping ^ 1;
            const int b = tid & 63;
            float psum = 0.0f;
#pragma unroll
            for (int q = 0; q < 2; ++q) {
                const int idx = tid + q * NTHR;
                const int j = idx >> 6;
                float vi = red0[(j)      * RST + b] + red1[(j)      * RST + b] + xgs[(j)      * RST + b];
                float vf = red0[(8 + j)  * RST + b] + red1[(8 + j)  * RST + b] + xgs[(8 + j)  * RST + b];
                float vg = red0[(16 + j) * RST + b] + red1[(16 + j) * RST + b] + xgs[(16 + j) * RST + b];
                float vo = red0[(24 + j) * RST + b] + red1[(24 + j) * RST + b] + xgs[(24 + j) * RST + b];
                float gi = sigm(vi), gf = sigm(vf), gg = ftanh(vg), go = sigm(vo);
                float cn = gf * cst[j * BB + b] + gi * gg;
                cst[j * BB + b] = cn;
                float hv = go * ftanh(cn);
                psum += hv * wo[j];
                const int u = u0 + j;
                const int rowk = u & 63;
                char* hhb = (char*)g_hhi + (size_t)(pingN * NCH + mychunk) * HT_B;
                uint32_t sw = sw128((uint32_t)(rowk * 128 + b * 2));
                *(__half*)(hhb + sw) = __float2half_rn(hv);
            }
            pr[(tid >> 6) * 64 + b] = psum;   // 256 distinct slots, conflict-free
        }
        // make h writes visible, then signal this CTA's chunk
        __threadfence();
        __syncthreads();
        if (tid < BB) {
            float s = pr[tid] + pr[64 + tid] + pr[128 + tid] + pr[192 + tid];
            g_partial[((size_t)blk * TT + t) * BB + tid] = s;
        }
        if (tid == 0) atomicAdd(&g_cflag[mychunk], 1u);
        // no grid barrier: next step's load_chunk polls producer flags
    }
}

// ---------------- k4: reduce partials -> out[b][t] ----------------
__global__ void k4_out(const float* __restrict__ b_out, float* __restrict__ out) {
    int g = blockIdx.x * blockDim.x + threadIdx.x;
    int b = g & 63;
    int t = g >> 6;
    float acc = b_out[0];
#pragma unroll 8
    for (int blk = 0; blk < NCTA; ++blk)
        acc += g_partial[((size_t)blk * TT + t) * BB + b];
    out[b * TT + t] = acc;
}

extern "C" void kernel_launch(void* const* d_in, const int* in_sizes, int n_in,
                              void* d_out, int out_size) {
    const float* latent = (const float*)d_in[0];
    const float* W_lin  = (const float*)d_in[1];
    const float* b_lin  = (const float*)d_in[2];
    const float* W_ih   = (const float*)d_in[3];
    const float* W_hh   = (const float*)d_in[4];
    const float* b_ih   = (const float*)d_in[5];
    const float* b_hh   = (const float*)d_in[6];
    const float* W_out  = (const float*)d_in[7];
    const float* b_out  = (const float*)d_in[8];
    float* out = (float*)d_out;

    cudaFuncSetAttribute(k3_lstm, cudaFuncAttributeMaxDynamicSharedMemorySize, SMEM_TOTAL);

    kW<<<2048, 256>>>(W_hh);
    k0_init<<<512, 256>>>();
    k1_hidden<<<(BB * HH) / 256, 256>>>(latent, W_lin, b_lin);
    k2_xgates<<<256, 256>>>(W_ih, b_ih, b_hh);
    k3_lstm<<<NCTA, NTHR, SMEM_TOTAL>>>(W_out);
    k4_out<<<(BB * TT) / 256, 256>>>(b_out, out);
}

// round 15
// speedup vs baseline: 1.7477x; 1.7477x over previous
#include <cuda_runtime.h>
#include <cuda_fp16.h>
#include <cstdint>

#define BB 64
#define LL 128
#define HH 1024
#define TT 256

#define NCTA 128
#define NTHR 256
#define UPB 8             // hidden units per CTA
#define MR 32             // gate rows per CTA (4 gates x 8 units)
#define NCH 8             // chunks per step (K=128 each)

#define WT_B 4096         // W sub-tile bytes: 32 rows x 128B (64 k)
#define WSLICE_B 65536    // per-CTA W hi (or lo) slice: 16 sub-tiles x 4KB
#define HT_B 16384        // h chunk bytes: 128 k-rows x 128B
#define HSUB_B 8192       // h sub-tile (64 k)

// smem byte offsets (k3)
#define SM_W    0                       // Whi[16] | Wlo[16] = 131072
#define SM_RING 131072                  // 4 x 16384 = 65536
#define SM_XG   196608                  // 32*66 floats = 8448
#define SM_RED  205056                  // 2*32*66 floats = 16896
#define SM_CST  221952                  // 8*64 floats = 2048
#define SM_WO   224000                  // 8 floats = 32
#define SM_PR   224032                  // 4*64 floats = 1024
#define SMEM_TOTAL 225056

#define RST 66

// ---------------- device scratch ----------------
__device__ __align__(16) __half g_Whi[NCTA*16*2048];     // 16 sub-tiles x 4KB per CTA
__device__ __align__(16) __half g_Wlo[NCTA*16*2048];
__device__ __align__(16) __half g_hhi[2*16*64*BB];       // ping-pong swizzled h, 16 sub-tiles
__device__ float g_hiddenT[HH*BB];           // [k][b] transposed hidden
__device__ float g_xg[4*HH*BB];              // [gate_row][b]
__device__ float g_partial[NCTA*TT*BB];
__device__ unsigned g_arrive, g_release;

// ---------------- helpers ----------------
__device__ __forceinline__ uint32_t smem_u32(const void* p) {
    uint32_t a;
    asm("{ .reg .u64 t; cvta.to.shared.u64 t, %1; cvt.u32.u64 %0, t; }" : "=r"(a) : "l"(p));
    return a;
}
__device__ __forceinline__ void cp16(void* dst, const void* src) {
    unsigned sa = (unsigned)__cvta_generic_to_shared(dst);
    asm volatile("cp.async.cg.shared.global [%0], [%1], 16;" :: "r"(sa), "l"(src));
}
__device__ __forceinline__ uint32_t sw128(uint32_t o) { return o ^ ((o >> 3) & 0x70); }

__device__ __forceinline__ void ldsm4(uint32_t* r, uint32_t a) {
    asm volatile("ldmatrix.sync.aligned.m8n8.x4.shared.b16 {%0,%1,%2,%3}, [%4];"
        : "=r"(r[0]), "=r"(r[1]), "=r"(r[2]), "=r"(r[3]) : "r"(a));
}
__device__ __forceinline__ void ldsm4t(uint32_t* r, uint32_t a) {
    asm volatile("ldmatrix.sync.aligned.m8n8.x4.trans.shared.b16 {%0,%1,%2,%3}, [%4];"
        : "=r"(r[0]), "=r"(r[1]), "=r"(r[2]), "=r"(r[3]) : "r"(a));
}
__device__ __forceinline__ void mma16816(float* d, const uint32_t* a, uint32_t b0, uint32_t b1) {
    asm volatile("mma.sync.aligned.m16n8k16.row.col.f32.f16.f16.f32 "
        "{%0,%1,%2,%3}, {%4,%5,%6,%7}, {%8,%9}, {%0,%1,%2,%3};"
        : "+f"(d[0]), "+f"(d[1]), "+f"(d[2]), "+f"(d[3])
        : "r"(a[0]), "r"(a[1]), "r"(a[2]), "r"(a[3]), "r"(b0), "r"(b1));
}
__device__ __forceinline__ float sigm(float x) { return 1.0f / (1.0f + __expf(-x)); }
__device__ __forceinline__ float ftanh(float x) { return 1.0f - 2.0f / (__expf(2.0f * x) + 1.0f); }

// ---------------- kW: split W_hh -> fp16 hi/lo swizzled tiles (8 k / thread) ----------------
__global__ void kW(const float* __restrict__ W_hh) {
    int idx = blockIdx.x * 256 + threadIdx.x;       // 524288 threads
    int R = idx >> 7;           // gate row 0..4095
    int k0 = (idx & 127) * 8;   // first of 8 consecutive k
    int gate = R >> 10;
    int u = R & 1023;
    int cta = u >> 3, j = u & 7;
    int m = gate * 8 + j;       // local row 0..31
    int ch = k0 >> 6, col = k0 & 63;
    uint32_t sw = sw128((uint32_t)(m * 128 + col * 2));   // 16B-aligned, chunk-contiguous
    const float4* src = (const float4*)(W_hh + (size_t)R * HH + k0);
    float4 a = src[0], b = src[1];
    float v[8] = {a.x, a.y, a.z, a.w, b.x, b.y, b.z, b.w};
    __half hi[8]; __half lo[8];
#pragma unroll
    for (int i = 0; i < 8; ++i) {
        hi[i] = __float2half_rn(v[i]);
        lo[i] = __float2half_rn(v[i] - __half2float(hi[i]));
    }
    size_t tb = (size_t)(cta * 16 + ch) * WT_B;
    *(uint4*)((char*)g_Whi + tb + sw) = *(const uint4*)hi;
    *(uint4*)((char*)g_Wlo + tb + sw) = *(const uint4*)lo;
}

// ---------------- k0: zero h buffers + counters ----------------
__global__ void k0_init() {
    int g = blockIdx.x * blockDim.x + threadIdx.x;  // 131072
    if (g < 2 * 16 * 64 * BB) g_hhi[g] = __float2half_rn(0.0f);
    if (g == 0) { g_arrive = 0u; g_release = 0u; }
}

// ---------------- k1: hidden (transposed [k][b] output) ----------------
__global__ void k1_hidden(const float* __restrict__ latent,
                          const float* __restrict__ W_lin,
                          const float* __restrict__ b_lin) {
    int g = blockIdx.x * blockDim.x + threadIdx.x;
    int k = g >> 6, b = g & 63;
    float acc = b_lin[k];
    const float* lr = latent + b * LL;
    const float* wr = W_lin + k * LL;
#pragma unroll 8
    for (int l = 0; l < LL; ++l) acc += lr[l] * wr[l];
    g_hiddenT[k * BB + b] = acc;
}

// ---------------- k2: x_gates, smem-staged hidden, 2 rows/thread (R13 proven) ----------------
__global__ void k2_xgates(const float* __restrict__ W_ih,
                          const float* __restrict__ b_ih,
                          const float* __restrict__ b_hh) {
    __shared__ float sh[64 * BB];    // 16KB
    const int tid = threadIdx.x;
    const int rr = tid >> 6, b = tid & 63;
    const int rA = blockIdx.x * 8 + rr;       // grid 512
    const int rB = rA + 4;
    float accA = b_ih[rA] + b_hh[rA];
    float accB = b_ih[rB] + b_hh[rB];
    const float4* wA = (const float4*)(W_ih + (size_t)rA * HH);
    const float4* wB = (const float4*)(W_ih + (size_t)rB * HH);

    for (int ch = 0; ch < 16; ++ch) {
        __syncthreads();
        const float4* src = (const float4*)(g_hiddenT + ch * 64 * BB);
        float4* dst = (float4*)sh;
#pragma unroll
        for (int i = 0; i < 4; ++i) dst[tid + i * 256] = src[tid + i * 256];
        __syncthreads();
#pragma unroll
        for (int kq = 0; kq < 16; ++kq) {
            float4 wa = wA[ch * 16 + kq];
            float4 wb = wB[ch * 16 + kq];
            float h0 = sh[(kq * 4 + 0) * BB + b];
            float h1 = sh[(kq * 4 + 1) * BB + b];
            float h2 = sh[(kq * 4 + 2) * BB + b];
            float h3 = sh[(kq * 4 + 3) * BB + b];
            accA += h0 * wa.x + h1 * wa.y + h2 * wa.z + h3 * wa.w;
            accB += h0 * wb.x + h1 * wb.y + h2 * wb.z + h3 * wb.w;
        }
    }
    g_xg[(size_t)rA * BB + b] = accA;
    g_xg[(size_t)rB * BB + b] = accB;
}

// ---------------- chunk loader: 16KB h chunk (4 cp16/thread) ----------------
__device__ __forceinline__ void load_chunk(char* sm, int ping, int c, int tid) {
    char* st = sm + SM_RING + (c & 3) * HT_B;
    const char* hh = (const char*)g_hhi + (size_t)(ping * 16 + 2 * c) * HSUB_B;
    int o = tid * 16;
#pragma unroll
    for (int i = 0; i < 4; ++i) cp16(st + i * 4096 + o, hh + i * 4096 + o);
    asm volatile("cp.async.commit_group;");
}

// ---------------- k3: persistent HMMA LSTM, W resident, 8 chunks ----------------
__global__ void __launch_bounds__(NTHR, 1)
k3_lstm(const float* __restrict__ W_out) {
    extern __shared__ char sm[];
    uint32_t smb = smem_u32(sm);
    float* wo  = (float*)(sm + SM_WO);
    float* cst = (float*)(sm + SM_CST);
    float* xgs = (float*)(sm + SM_XG);
    float* red0 = (float*)(sm + SM_RED);
    float* red1 = red0 + MR * RST;
    float* pr  = (float*)(sm + SM_PR);

    const int tid = threadIdx.x, blk = blockIdx.x;
    const int wid = tid >> 5, lane = tid & 31;
    const int ks = wid & 1;            // K-slice (32 of each 64-k sub-tile)
    const int ng = (wid >> 1) & 1;     // N-half (n32)
    const int mh = wid >> 2;           // M-half (m16)
    const int u0 = blk * UPB;

    // per-lane swizzled ldmatrix offsets (within a 4KB W sub-tile / 8KB h sub-tile)
    uint32_t offA[2], offB[2][2];
#pragma unroll
    for (int kt = 0; kt < 2; ++kt) {
        uint32_t o = (uint32_t)((mh * 16 + (lane & 15)) * 128 + ks * 64 + kt * 32 + (lane >> 4) * 16);
        offA[kt] = sw128(o);
    }
#pragma unroll
    for (int kt = 0; kt < 2; ++kt)
#pragma unroll
        for (int np = 0; np < 2; ++np) {
            uint32_t o = (uint32_t)((ks * 32 + kt * 16 + (lane & 15)) * 128 + ng * 64 + np * 32 + (lane >> 4) * 16);
            offB[kt][np] = sw128(o);
        }

    // ---- prologue: W hi/lo slice -> smem (once), x_gates slice, c-state ----
    {
        const char* wh = (const char*)g_Whi + (size_t)blk * WSLICE_B;
        const char* wl = (const char*)g_Wlo + (size_t)blk * WSLICE_B;
#pragma unroll
        for (int i = 0; i < 16; ++i) {
            int o = (tid + i * NTHR) * 16;
            cp16(sm + SM_W + o, wh + o);
            cp16(sm + SM_W + WSLICE_B + o, wl + o);
        }
        asm volatile("cp.async.commit_group;");
    }
    for (int idx = tid; idx < MR * BB; idx += NTHR) {
        int m = idx >> 6, b = idx & 63;
        int gate = m >> 3, j = m & 7;
        xgs[m * RST + b] = g_xg[(size_t)(gate * HH + u0 + j) * BB + b];
    }
    if (tid < UPB) wo[tid] = W_out[u0 + tid];
    for (int i = tid; i < UPB * BB; i += NTHR) cst[i] = 0.0f;
    asm volatile("cp.async.wait_group 0;");
    __syncthreads();

    for (int t = 0; t < TT; ++t) {
        const int ping = t & 1;

        load_chunk(sm, ping, 0, tid);
        load_chunk(sm, ping, 1, tid);
        load_chunk(sm, ping, 2, tid);

        // separate hi/lo accumulator banks (8 independent mma chains)
        float ah[4][4], al[4][4];
#pragma unroll
        for (int n = 0; n < 4; ++n)
#pragma unroll
            for (int q = 0; q < 4; ++q) { ah[n][q] = 0.0f; al[n][q] = 0.0f; }

        for (int c = 0; c < NCH; ++c) {
            if (c <= 5)       asm volatile("cp.async.wait_group 2;");
            else if (c == 6)  asm volatile("cp.async.wait_group 1;");
            else              asm volatile("cp.async.wait_group 0;");
            __syncthreads();

            const uint32_t hstage = smb + SM_RING + (uint32_t)((c & 3) * HT_B);
#pragma unroll
            for (int sub = 0; sub < 2; ++sub) {
                const uint32_t wbase = smb + SM_W + (uint32_t)((2 * c + sub) * WT_B);
                const uint32_t hbase = hstage + (uint32_t)(sub * HSUB_B);
#pragma unroll
                for (int kt = 0; kt < 2; ++kt) {
                    uint32_t Ahi[4], Alo[4], B0[4], B1[4];
                    ldsm4(Ahi, wbase + offA[kt]);
                    ldsm4(Alo, wbase + WSLICE_B + offA[kt]);
                    ldsm4t(B0, hbase + offB[kt][0]);
                    ldsm4t(B1, hbase + offB[kt][1]);
                    mma16816(ah[0], Ahi, B0[0], B0[1]);
                    mma16816(ah[1], Ahi, B0[2], B0[3]);
                    mma16816(ah[2], Ahi, B1[0], B1[1]);
                    mma16816(ah[3], Ahi, B1[2], B1[3]);
                    mma16816(al[0], Alo, B0[0], B0[1]);
                    mma16816(al[1], Alo, B0[2], B0[3]);
                    mma16816(al[2], Alo, B1[0], B1[1]);
                    mma16816(al[3], Alo, B1[2], B1[3]);
                }
            }

            if (c + 3 < NCH) load_chunk(sm, ping, c + 3, tid);
        }

        // ---- store combined partials to red[ks] ----
        {
            float* rd = ks ? red1 : red0;
            const int r0 = lane >> 2, c0 = (lane & 3) * 2;
#pragma unroll
            for (int n = 0; n < 4; ++n) {
                int row = mh * 16 + r0;
                int col = ng * 32 + n * 8 + c0;
                rd[row * RST + col]           = ah[n][0] + al[n][0];
                rd[row * RST + col + 1]       = ah[n][1] + al[n][1];
                rd[(row + 8) * RST + col]     = ah[n][2] + al[n][2];
                rd[(row + 8) * RST + col + 1] = ah[n][3] + al[n][3];
            }
        }
        __syncthreads();

        // ---- gates + state update: 512 states, 2 per thread; no atomics ----
        {
            const int pingN = ping ^ 1;
            const int b = tid & 63;
            float psum = 0.0f;
#pragma unroll
            for (int q = 0; q < 2; ++q) {
                const int idx = tid + q * NTHR;
                const int j = idx >> 6;
                float vi = red0[(j)      * RST + b] + red1[(j)      * RST + b] + xgs[(j)      * RST + b];
                float vf = red0[(8 + j)  * RST + b] + red1[(8 + j)  * RST + b] + xgs[(8 + j)  * RST + b];
                float vg = red0[(16 + j) * RST + b] + red1[(16 + j) * RST + b] + xgs[(16 + j) * RST + b];
                float vo = red0[(24 + j) * RST + b] + red1[(24 + j) * RST + b] + xgs[(24 + j) * RST + b];
                float gi = sigm(vi), gf = sigm(vf), gg = ftanh(vg), go = sigm(vo);
                float cn = gf * cst[j * BB + b] + gi * gg;
                cst[j * BB + b] = cn;
                float hv = go * ftanh(cn);
                psum += hv * wo[j];
                const int u = u0 + j;
                const int chn = u >> 6, rowk = u & 63;
                char* hhb = (char*)g_hhi + (size_t)(pingN * 16 + chn) * HSUB_B;
                uint32_t sw = sw128((uint32_t)(rowk * 128 + b * 2));
                *(__half*)(hhb + sw) = __float2half_rn(hv);
            }
            pr[(tid >> 6) * 64 + b] = psum;   // 256 distinct slots, conflict-free
        }
        __syncthreads();
        if (tid < BB) {
            float s = pr[tid] + pr[64 + tid] + pr[128 + tid] + pr[192 + tid];
            g_partial[((size_t)blk * TT + t) * BB + tid] = s;
        }
        __threadfence();
        __syncthreads();

        // ---- grid barrier (monotonic counters) ----
        if (tid == 0) {
            unsigned tgt = (unsigned)(t + 1);
            unsigned arr = atomicAdd(&g_arrive, 1u) + 1u;
            if (arr == (unsigned)NCTA * tgt) {
                atomicExch(&g_release, tgt);
            } else {
                while (*(volatile unsigned*)&g_release < tgt) { }
            }
            __threadfence();
        }
        __syncthreads();
    }
}

// ---------------- k4: reduce partials -> out[b][t] ----------------
__global__ void k4_out(const float* __restrict__ b_out, float* __restrict__ out) {
    int g = blockIdx.x * blockDim.x + threadIdx.x;
    int b = g & 63;
    int t = g >> 6;
    float acc = b_out[0];
#pragma unroll 8
    for (int blk = 0; blk < NCTA; ++blk)
        acc += g_partial[((size_t)blk * TT + t) * BB + b];
    out[b * TT + t] = acc;
}

extern "C" void kernel_launch(void* const* d_in, const int* in_sizes, int n_in,
                              void* d_out, int out_size) {
    const float* latent = (const float*)d_in[0];
    const float* W_lin  = (const float*)d_in[1];
    const float* b_lin  = (const float*)d_in[2];
    const float* W_ih   = (const float*)d_in[3];
    const float* W_hh   = (const float*)d_in[4];
    const float* b_ih   = (const float*)d_in[5];
    const float* b_hh   = (const float*)d_in[6];
    const float* W_out  = (const float*)d_in[7];
    const float* b_out  = (const float*)d_in[8];
    float* out = (float*)d_out;

    cudaFuncSetAttribute(k3_lstm, cudaFuncAttributeMaxDynamicSharedMemorySize, SMEM_TOTAL);

    kW<<<2048, 256>>>(W_hh);
    k0_init<<<512, 256>>>();
    k1_hidden<<<(BB * HH) / 256, 256>>>(latent, W_lin, b_lin);
    k2_xgates<<<512, 256>>>(W_ih, b_ih, b_hh);
    k3_lstm<<<NCTA, NTHR, SMEM_TOTAL>>>(W_out);
    k4_out<<<(BB * TT) / 256, 256>>>(b_out, out);
}